// round 1
// baseline (speedup 1.0000x reference)
#include <cuda_runtime.h>
#include <cstdint>

// Problem constants
#define T_STEPS 1000
#define BATCH   2048
#define FEAT    40
#define H1      8
#define H2      6
#define G1      32          // 4*H1
#define G2      24          // 4*H2
#define NPAIR   1024        // BATCH/2

typedef unsigned long long u64;

// Scratch: precomputed layer-1 input gates, layout [t][pair][gate], each u64 = float2 {b=2w, b=2w+1}
// 1000 * 1024 * 32 * 8B = 262 MB
__device__ u64 g_xg[(size_t)T_STEPS * NPAIR * G1];

// ---------------- f32x2 helpers ----------------
__device__ __forceinline__ u64 pack2(float x, float y) {
    u64 r;
    asm("mov.b64 %0, {%1, %2};" : "=l"(r) : "f"(x), "f"(y));
    return r;
}
__device__ __forceinline__ void unpack2(u64 v, float& x, float& y) {
    asm("mov.b64 {%0, %1}, %2;" : "=f"(x), "=f"(y) : "l"(v));
}
__device__ __forceinline__ u64 fma2(u64 a, u64 b, u64 c) {
    u64 d;
    asm("fma.rn.f32x2 %0, %1, %2, %3;" : "=l"(d) : "l"(a), "l"(b), "l"(c));
    return d;
}

// ---------------- activations (safe/accurate this round) ----------------
// Unified form: act(x) = ca + cn / (1 + exp(cm * x))
//   sigmoid: cm=-1, cn=1, ca=0
//   tanh   : cm=-2, cn=2, ca=-1
__device__ __forceinline__ float actf(float x, float cm, float cn, float ca) {
    return ca + __fdividef(cn, 1.0f + __expf(cm * x));
}
__device__ __forceinline__ float tanh_act(float x) { return actf(x, -2.0f, 2.0f, -1.0f); }
__device__ __forceinline__ float sig_act(float x)  { return actf(x, -1.0f, 1.0f,  0.0f); }

// ============================================================================
// Kernel 1: input projection  xg[t][w][g] = {row 2w, row 2w+1} dot W_ih1[g] + b
// One thread per (pair w, time t). f32x2 packs the two batch rows.
// ============================================================================
#define PROJ_BLK 128

__global__ void proj_kernel(const float* __restrict__ x,
                            const float* __restrict__ W,
                            const float* __restrict__ bi,
                            const float* __restrict__ bh) {
    __shared__ __align__(16) u64 Wsh[FEAT * G1];  // [f*32 + g] = {W[g][f], W[g][f]}
    __shared__ u64 Bsh[G1];

    int tid = threadIdx.x;
    for (int i = tid; i < FEAT * G1; i += PROJ_BLK) {
        int f = i >> 5, g = i & 31;
        float v = W[g * FEAT + f];
        Wsh[i] = pack2(v, v);
    }
    if (tid < G1) {
        float v = bi[tid] + bh[tid];
        Bsh[tid] = pack2(v, v);
    }
    __syncthreads();

    int idx = blockIdx.x * PROJ_BLK + tid;            // exactly NPAIR*T_STEPS threads
    int t = idx % T_STEPS;
    int w = idx / T_STEPS;

    const float4* x0 = reinterpret_cast<const float4*>(x + ((size_t)(2 * w)     * T_STEPS + t) * FEAT);
    const float4* x1 = reinterpret_cast<const float4*>(x + ((size_t)(2 * w + 1) * T_STEPS + t) * FEAT);

    u64 acc[G1];
#pragma unroll
    for (int g = 0; g < G1; g++) acc[g] = Bsh[g];

#pragma unroll 1
    for (int fc = 0; fc < FEAT / 4; fc++) {
        float4 a = x0[fc];
        float4 b = x1[fc];
        u64 xp[4] = { pack2(a.x, b.x), pack2(a.y, b.y), pack2(a.z, b.z), pack2(a.w, b.w) };
#pragma unroll
        for (int k = 0; k < 4; k++) {
            int f = fc * 4 + k;
            const ulonglong2* wp = reinterpret_cast<const ulonglong2*>(&Wsh[f * G1]);
#pragma unroll
            for (int p = 0; p < 16; p++) {
                ulonglong2 wv = wp[p];                 // LDS.128: 2 duplicated weights
                acc[2 * p]     = fma2(xp[k], wv.x, acc[2 * p]);
                acc[2 * p + 1] = fma2(xp[k], wv.y, acc[2 * p + 1]);
            }
        }
    }

    u64* outp = g_xg + ((size_t)t * NPAIR + w) * G1;
#pragma unroll
    for (int g = 0; g < G1; g++) outp[g] = acc[g];
}

// ============================================================================
// Kernel 2: recurrence. 1024 warps; warp w owns batch elems (2w, 2w+1) packed
// in f32x2. Lane = layer1 gate (32) / layer2 gate (lanes 0-23).
// Hidden-state broadcast through per-warp shared slabs, double-buffered.
// ============================================================================
#define REC_BLK 64
#define WPB     2   // warps per block

__global__ void __launch_bounds__(REC_BLK, 1)
rec_kernel(const float* __restrict__ W_hh1,
           const float* __restrict__ W_ih2,
           const float* __restrict__ W_hh2,
           const float* __restrict__ b_ih2,
           const float* __restrict__ b_hh2,
           const float* __restrict__ W_fc,
           const float* __restrict__ b_fc,
           float* __restrict__ out) {
    // [warp][slot][idx]: idx 0..7 = h1, 8..15 = x2(=tanh h1), 16..21 = h2
    __shared__ u64 sh[WPB][2][22];

    int lane = threadIdx.x & 31;
    int wib  = threadIdx.x >> 5;
    int w    = blockIdx.x * WPB + wib;

    // ---- per-lane weights (duplicated into both f32x2 halves) ----
    u64 w1[H1];
#pragma unroll
    for (int j = 0; j < H1; j++) {
        float v = W_hh1[lane * H1 + j];
        w1[j] = pack2(v, v);
    }
    u64 wi2[H1], wh2[H2], bias2;
#pragma unroll
    for (int j = 0; j < H1; j++) wi2[j] = 0ull;
#pragma unroll
    for (int j = 0; j < H2; j++) wh2[j] = 0ull;
    bias2 = 0ull;
    if (lane < G2) {
#pragma unroll
        for (int j = 0; j < H1; j++) { float v = W_ih2[lane * H1 + j]; wi2[j] = pack2(v, v); }
#pragma unroll
        for (int j = 0; j < H2; j++) { float v = W_hh2[lane * H2 + j]; wh2[j] = pack2(v, v); }
        float bb = b_ih2[lane] + b_hh2[lane];
        bias2 = pack2(bb, bb);
    }

    // ---- per-lane activation constants (tanh for the cell-gate quarter) ----
    bool t1 = ((lane >> 3) == 2);
    float cm1 = t1 ? -2.f : -1.f, cn1 = t1 ? 2.f : 1.f, ca1 = t1 ? -1.f : 0.f;
    bool t2 = ((lane / 6) == 2);
    float cm2 = t2 ? -2.f : -1.f, cn2 = t2 ? 2.f : 1.f, ca2 = t2 ? -1.f : 0.f;

    u64 (*sl)[22] = sh[wib];
    if (lane < H1) sl[0][lane] = 0ull;       // h1 = 0
    if (lane < H2) sl[0][16 + lane] = 0ull;  // h2 = 0
    __syncwarp();

    const u64* xgp = g_xg + (size_t)w * G1 + lane;
    float c1x = 0.f, c1y = 0.f, c2x = 0.f, c2y = 0.f;

#pragma unroll 2
    for (int t = 0; t < T_STEPS; t++) {
        int r = t & 1, s = r ^ 1;

        // ---------- layer 1 ----------
        u64 g1 = *xgp;                        // precomputed x-proj + biases
        xgp += (size_t)NPAIR * G1;
#pragma unroll
        for (int j = 0; j < H1; j++) g1 = fma2(sl[r][j], w1[j], g1);

        float gx, gy; unpack2(g1, gx, gy);
        float ax = actf(gx, cm1, cn1, ca1);
        float ay = actf(gy, cm1, cn1, ca1);

        float fx  = __shfl_sync(0xffffffffu, ax, (lane + 8)  & 31);
        float fy  = __shfl_sync(0xffffffffu, ay, (lane + 8)  & 31);
        float ggx = __shfl_sync(0xffffffffu, ax, (lane + 16) & 31);
        float ggy = __shfl_sync(0xffffffffu, ay, (lane + 16) & 31);
        float ox  = __shfl_sync(0xffffffffu, ax, (lane + 24) & 31);
        float oy  = __shfl_sync(0xffffffffu, ay, (lane + 24) & 31);

        c1x = fmaf(fx, c1x, ax * ggx);        // c = f*c + i*g   (valid on lanes 0-7)
        c1y = fmaf(fy, c1y, ay * ggy);
        float h1x = ox * tanh_act(c1x);
        float h1y = oy * tanh_act(c1y);
        float x2x = tanh_act(h1x);            // inter-layer tanh
        float x2y = tanh_act(h1y);

        if (lane < H1) {
            sl[s][lane]     = pack2(h1x, h1y);
            sl[s][8 + lane] = pack2(x2x, x2y);
        }
        __syncwarp();

        // ---------- layer 2 ----------
        u64 g2 = bias2;
#pragma unroll
        for (int j = 0; j < H1; j++) g2 = fma2(sl[s][8 + j],  wi2[j], g2);
#pragma unroll
        for (int j = 0; j < H2; j++) g2 = fma2(sl[r][16 + j], wh2[j], g2);

        float g2x, g2y; unpack2(g2, g2x, g2y);
        float a2x = actf(g2x, cm2, cn2, ca2);
        float a2y = actf(g2y, cm2, cn2, ca2);

        float f2x  = __shfl_sync(0xffffffffu, a2x, (lane + 6)  & 31);
        float f2y  = __shfl_sync(0xffffffffu, a2y, (lane + 6)  & 31);
        float gg2x = __shfl_sync(0xffffffffu, a2x, (lane + 12) & 31);
        float gg2y = __shfl_sync(0xffffffffu, a2y, (lane + 12) & 31);
        float o2x  = __shfl_sync(0xffffffffu, a2x, (lane + 18) & 31);
        float o2y  = __shfl_sync(0xffffffffu, a2y, (lane + 18) & 31);

        c2x = fmaf(f2x, c2x, a2x * gg2x);     // valid on lanes 0-5
        c2y = fmaf(f2y, c2y, a2y * gg2y);
        float h2x = o2x * tanh_act(c2x);
        float h2y = o2y * tanh_act(c2y);

        if (lane < H2) sl[s][16 + lane] = pack2(h2x, h2y);
        __syncwarp();
    }

    // ---------- final FC + sigmoid (t=999 wrote slot 0) ----------
    if (lane == 0) {
        float bf = b_fc[0];
        float sx = bf, sy = bf;
#pragma unroll
        for (int j = 0; j < H2; j++) {
            float hx, hy; unpack2(sl[0][16 + j], hx, hy);
            float wf = W_fc[j];
            sx = fmaf(tanh_act(hx), wf, sx);
            sy = fmaf(tanh_act(hy), wf, sy);
        }
        out[2 * w]     = sig_act(sx);
        out[2 * w + 1] = sig_act(sy);
    }
}

// ============================================================================
// Launch
// ============================================================================
extern "C" void kernel_launch(void* const* d_in, const int* in_sizes, int n_in,
                              void* d_out, int out_size) {
    const float* x     = (const float*)d_in[0];
    const float* W_ih1 = (const float*)d_in[1];
    const float* W_hh1 = (const float*)d_in[2];
    const float* b_ih1 = (const float*)d_in[3];
    const float* b_hh1 = (const float*)d_in[4];
    const float* W_ih2 = (const float*)d_in[5];
    const float* W_hh2 = (const float*)d_in[6];
    const float* b_ih2 = (const float*)d_in[7];
    const float* b_hh2 = (const float*)d_in[8];
    const float* W_fc  = (const float*)d_in[9];
    const float* b_fc  = (const float*)d_in[10];
    float* out = (float*)d_out;

    int proj_threads = NPAIR * T_STEPS;                 // 1,024,000
    proj_kernel<<<proj_threads / PROJ_BLK, PROJ_BLK>>>(x, W_ih1, b_ih1, b_hh1);

    rec_kernel<<<NPAIR / WPB, REC_BLK>>>(W_hh1, W_ih2, W_hh2, b_ih2, b_hh2,
                                         W_fc, b_fc, out);
}

// round 2
// speedup vs baseline: 1.9320x; 1.9320x over previous
#include <cuda_runtime.h>
#include <cstdint>

#define T_STEPS 1000
#define BATCH   2048
#define FEAT    40
#define H1      8
#define H2      6
#define G1      32
#define G2      24
#define NPAIR   1024

typedef unsigned long long u64;

// gates scratch: [pair][t][gate], u64 = float2 {batch 2w, 2w+1}. 262 MB.
__device__ u64 g_xg[(size_t)NPAIR * T_STEPS * G1];

// ---------------- f32x2 helpers ----------------
__device__ __forceinline__ u64 pack2(float x, float y) {
    u64 r; asm("mov.b64 %0, {%1, %2};" : "=l"(r) : "f"(x), "f"(y)); return r;
}
__device__ __forceinline__ void unpack2(u64 v, float& x, float& y) {
    asm("mov.b64 {%0, %1}, %2;" : "=f"(x), "=f"(y) : "l"(v));
}
__device__ __forceinline__ u64 fma2(u64 a, u64 b, u64 c) {
    u64 d; asm("fma.rn.f32x2 %0, %1, %2, %3;" : "=l"(d) : "l"(a), "l"(b), "l"(c)); return d;
}
__device__ __forceinline__ u64 mul2(u64 a, u64 b) {
    u64 d; asm("mul.rn.f32x2 %0, %1, %2;" : "=l"(d) : "l"(a), "l"(b)); return d;
}
__device__ __forceinline__ u64 add2(u64 a, u64 b) {
    u64 d; asm("add.rn.f32x2 %0, %1, %2;" : "=l"(d) : "l"(a), "l"(b)); return d;
}

// ---------------- activations: 5 inst, 2 MUFU ----------------
__device__ __forceinline__ float ex2a(float x) {
    float r; asm("ex2.approx.ftz.f32 %0, %1;" : "=f"(r) : "f"(x)); return r;
}
__device__ __forceinline__ float rcpa(float x) {
    float r; asm("rcp.approx.ftz.f32 %0, %1;" : "=f"(r) : "f"(x)); return r;
}
// act(x) = ca + cn * rcp(1 + 2^(cm*x));  cm carries the log2(e) factor.
__device__ __forceinline__ float actf(float x, float cm, float cn, float ca) {
    return fmaf(cn, rcpa(1.0f + ex2a(cm * x)), ca);
}
#define LOG2E   1.4426950408889634f
#define TANH_CM (-2.8853900817779268f)   // -2*log2(e)
__device__ __forceinline__ float tanhfast(float x) {
    return actf(x, TANH_CM, 2.0f, -1.0f);
}

// ============================================================================
// Kernel 1: projection. Thread = (pair w, t). t-consecutive threads.
// Output staged via shared for contiguous 32KB global writes.
// ============================================================================
#define PBLK   128
#define PCHUNK 125   // 1000 = 8 * 125

__global__ void __launch_bounds__(PBLK)
proj_kernel(const float* __restrict__ x,
            const float* __restrict__ W,
            const float* __restrict__ bi,
            const float* __restrict__ bh) {
    __shared__ __align__(16) u64 Wsh[FEAT * G1];      // [f*32+g], duplicated pair
    __shared__ u64 Bsh[G1];
    __shared__ u64 Ssh[G1 * PCHUNK];                  // [g*125 + i]

    int tid = threadIdx.x;
    int w   = blockIdx.y;
    int t0  = blockIdx.x * PCHUNK;

    for (int i = tid; i < FEAT * G1; i += PBLK) {
        int f = i >> 5, g = i & 31;
        float v = W[g * FEAT + f];
        Wsh[i] = pack2(v, v);
    }
    if (tid < G1) {
        float v = bi[tid] + bh[tid];
        Bsh[tid] = pack2(v, v);
    }
    __syncthreads();

    if (tid < PCHUNK) {
        int t = t0 + tid;
        const float4* x0 = reinterpret_cast<const float4*>(x + ((size_t)(2 * w)     * T_STEPS + t) * FEAT);
        const float4* x1 = reinterpret_cast<const float4*>(x + ((size_t)(2 * w + 1) * T_STEPS + t) * FEAT);

        u64 acc[G1];
#pragma unroll
        for (int g = 0; g < G1; g++) acc[g] = Bsh[g];

#pragma unroll 1
        for (int fc = 0; fc < FEAT / 4; fc++) {
            float4 a = x0[fc];
            float4 b = x1[fc];
            u64 xp[4] = { pack2(a.x, b.x), pack2(a.y, b.y), pack2(a.z, b.z), pack2(a.w, b.w) };
#pragma unroll
            for (int k = 0; k < 4; k++) {
                int f = fc * 4 + k;
                const ulonglong2* wp = reinterpret_cast<const ulonglong2*>(&Wsh[f * G1]);
#pragma unroll
                for (int p = 0; p < 16; p++) {
                    ulonglong2 wv = wp[p];
                    acc[2 * p]     = fma2(xp[k], wv.x, acc[2 * p]);
                    acc[2 * p + 1] = fma2(xp[k], wv.y, acc[2 * p + 1]);
                }
            }
        }
#pragma unroll
        for (int g = 0; g < G1; g++) Ssh[g * PCHUNK + tid] = acc[g];
    }
    __syncthreads();

    // contiguous write-out: element k of this block's region = Ssh[(k&31)*125 + (k>>5)]
    u64* outp = g_xg + ((size_t)w * T_STEPS + t0) * G1;
    for (int k = tid; k < PCHUNK * G1; k += PBLK)
        outp[k] = Ssh[(k & 31) * PCHUNK + (k >> 5)];
}

// ============================================================================
// Kernel 2: fused recurrence. 1 warp per pair (1024 warps).
// Iteration i computes layer1(i) and layer2(i-1) -> the two chains overlap.
// ============================================================================
__device__ __forceinline__ float shflf(float v, int src) {
    return __shfl_sync(0xffffffffu, v, src);
}

template <int RD>
__device__ __forceinline__ void lstm_step(
    int i, int lane, u64& xgb, const u64* __restrict__ xgp,
    u64 (*shs)[24],
    const u64* w1, const u64* wi2, const u64* wh2, u64 bias2,
    float cm1, float cn1, float ca1,
    float cm2, float cn2, float ca2,
    float& c1x, float& c1y, float& c2x, float& c2y)
{
    constexpr int WR = RD ^ 1;
    u64 xg = xgb;
    int tn = i + 4; if (tn > T_STEPS - 1) tn = T_STEPS - 1;
    xgb = xgp[(size_t)tn * G1];                       // prefetch, off-path

    // ---- layer1 MAC: g1 = xg + h1(i-1) . w1  (2 chains) ----
    u64 A = fma2(shs[RD][0], w1[0], xg);
    u64 B = mul2(shs[RD][1], w1[1]);
    A = fma2(shs[RD][2], w1[2], A);
    B = fma2(shs[RD][3], w1[3], B);
    A = fma2(shs[RD][4], w1[4], A);
    B = fma2(shs[RD][5], w1[5], B);
    A = fma2(shs[RD][6], w1[6], A);
    B = fma2(shs[RD][7], w1[7], B);
    u64 g1 = add2(A, B);

    // ---- layer2 MAC: g2 = bias2 + x2(i-1) . wi2 + h2(i-2) . wh2 (3 chains) ----
    u64 P = fma2(shs[RD][8],  wi2[0], bias2);
    u64 Q = mul2(shs[RD][9],  wi2[1]);
    u64 R = mul2(shs[RD][10], wi2[2]);
    P = fma2(shs[RD][11], wi2[3], P);
    Q = fma2(shs[RD][12], wi2[4], Q);
    R = fma2(shs[RD][13], wi2[5], R);
    P = fma2(shs[RD][14], wi2[6], P);
    Q = fma2(shs[RD][15], wi2[7], Q);
    R = fma2(shs[RD][16], wh2[0], R);
    P = fma2(shs[RD][17], wh2[1], P);
    Q = fma2(shs[RD][18], wh2[2], Q);
    R = fma2(shs[RD][19], wh2[3], R);
    P = fma2(shs[RD][20], wh2[4], P);
    Q = fma2(shs[RD][21], wh2[5], Q);
    u64 g2 = add2(add2(P, Q), R);

    // ---- activations (both layers issue together: MUFU overlap) ----
    float g1x, g1y; unpack2(g1, g1x, g1y);
    float g2x, g2y; unpack2(g2, g2x, g2y);
    float a1x = actf(g1x, cm1, cn1, ca1);
    float a1y = actf(g1y, cm1, cn1, ca1);
    float a2x = actf(g2x, cm2, cn2, ca2);
    float a2y = actf(g2y, cm2, cn2, ca2);

    // ---- gate gathers ----
    float f1x = shflf(a1x, lane + 8),  f1y = shflf(a1y, lane + 8);
    float i1x = shflf(a1x, lane + 16), i1y = shflf(a1y, lane + 16); // cell gate
    float o1x = shflf(a1x, lane + 24), o1y = shflf(a1y, lane + 24);
    float f2x = shflf(a2x, lane + 6),  f2y = shflf(a2y, lane + 6);
    float i2x = shflf(a2x, lane + 12), i2y = shflf(a2y, lane + 12);
    float o2x = shflf(a2x, lane + 18), o2y = shflf(a2y, lane + 18);

    float en = (i > 0) ? 1.0f : 0.0f;   // suppress bogus L2(-1) on first step

    // ---- layer1 state (valid lanes 0..7) ----
    c1x = fmaf(f1x, c1x, a1x * i1x);
    c1y = fmaf(f1y, c1y, a1y * i1y);
    float h1x = o1x * tanhfast(c1x);
    float h1y = o1y * tanhfast(c1y);
    float x2x = tanhfast(h1x);
    float x2y = tanhfast(h1y);

    // ---- layer2 state (valid lanes 0..5) ----
    c2x = en * fmaf(f2x, c2x, a2x * i2x);
    c2y = en * fmaf(f2y, c2y, a2y * i2y);
    float h2x = o2x * tanhfast(c2x);
    float h2y = o2y * tanhfast(c2y);

    if (lane < H1) {
        shs[WR][lane]      = pack2(h1x, h1y);
        shs[WR][8 + lane]  = pack2(x2x, x2y);
    }
    if (lane < H2) shs[WR][16 + lane] = pack2(h2x, h2y);
    __syncwarp();
}

__global__ void __launch_bounds__(32)
rec_kernel(const float* __restrict__ W_hh1,
           const float* __restrict__ W_ih2,
           const float* __restrict__ W_hh2,
           const float* __restrict__ b_ih2,
           const float* __restrict__ b_hh2,
           const float* __restrict__ W_fc,
           const float* __restrict__ b_fc,
           float* __restrict__ out) {
    __shared__ u64 shs[2][24];
    int lane = threadIdx.x;
    int w    = blockIdx.x;

    // per-lane weights, duplicated across f32x2 halves
    u64 w1[H1];
#pragma unroll
    for (int j = 0; j < H1; j++) { float v = W_hh1[lane * H1 + j]; w1[j] = pack2(v, v); }
    u64 wi2[H1], wh2[H2], bias2 = 0ull;
#pragma unroll
    for (int j = 0; j < H1; j++) wi2[j] = 0ull;
#pragma unroll
    for (int j = 0; j < H2; j++) wh2[j] = 0ull;
    if (lane < G2) {
#pragma unroll
        for (int j = 0; j < H1; j++) { float v = W_ih2[lane * H1 + j]; wi2[j] = pack2(v, v); }
#pragma unroll
        for (int j = 0; j < H2; j++) { float v = W_hh2[lane * H2 + j]; wh2[j] = pack2(v, v); }
        float bb = b_ih2[lane] + b_hh2[lane];
        bias2 = pack2(bb, bb);
    }

    // per-lane activation constants (cm includes log2e)
    bool t1 = ((lane >> 3) == 2);
    float cm1 = t1 ? TANH_CM : -LOG2E, cn1 = t1 ? 2.f : 1.f, ca1 = t1 ? -1.f : 0.f;
    bool t2 = (lane >= 12 && lane < 18);
    float cm2 = t2 ? TANH_CM : -LOG2E, cn2 = t2 ? 2.f : 1.f, ca2 = t2 ? -1.f : 0.f;

    // init: slab[1] = zeros (read by step 0)
    if (lane < 24) shs[1][lane] = 0ull;
    __syncwarp();

    const u64* xgp = g_xg + (size_t)w * T_STEPS * G1 + lane;
    u64 b0 = xgp[0], b1 = xgp[G1], b2 = xgp[2 * G1], b3 = xgp[3 * G1];
    float c1x = 0.f, c1y = 0.f, c2x = 0.f, c2y = 0.f;

#pragma unroll 1
    for (int ii = 0; ii < T_STEPS; ii += 4) {
        lstm_step<1>(ii + 0, lane, b0, xgp, shs, w1, wi2, wh2, bias2,
                     cm1, cn1, ca1, cm2, cn2, ca2, c1x, c1y, c2x, c2y);
        lstm_step<0>(ii + 1, lane, b1, xgp, shs, w1, wi2, wh2, bias2,
                     cm1, cn1, ca1, cm2, cn2, ca2, c1x, c1y, c2x, c2y);
        lstm_step<1>(ii + 2, lane, b2, xgp, shs, w1, wi2, wh2, bias2,
                     cm1, cn1, ca1, cm2, cn2, ca2, c1x, c1y, c2x, c2y);
        lstm_step<0>(ii + 3, lane, b3, xgp, shs, w1, wi2, wh2, bias2,
                     cm1, cn1, ca1, cm2, cn2, ca2, c1x, c1y, c2x, c2y);
    }

    // ---- epilogue: layer2(999) from slab[1] (h1/x2(999), h2(998)) ----
    u64 P = fma2(shs[1][8],  wi2[0], bias2);
    u64 Q = mul2(shs[1][9],  wi2[1]);
    u64 R = mul2(shs[1][10], wi2[2]);
    P = fma2(shs[1][11], wi2[3], P);
    Q = fma2(shs[1][12], wi2[4], Q);
    R = fma2(shs[1][13], wi2[5], R);
    P = fma2(shs[1][14], wi2[6], P);
    Q = fma2(shs[1][15], wi2[7], Q);
    R = fma2(shs[1][16], wh2[0], R);
    P = fma2(shs[1][17], wh2[1], P);
    Q = fma2(shs[1][18], wh2[2], Q);
    R = fma2(shs[1][19], wh2[3], R);
    P = fma2(shs[1][20], wh2[4], P);
    Q = fma2(shs[1][21], wh2[5], Q);
    u64 g2 = add2(add2(P, Q), R);

    float g2x, g2y; unpack2(g2, g2x, g2y);
    float a2x = actf(g2x, cm2, cn2, ca2);
    float a2y = actf(g2y, cm2, cn2, ca2);
    float f2x = shflf(a2x, lane + 6),  f2y = shflf(a2y, lane + 6);
    float i2x = shflf(a2x, lane + 12), i2y = shflf(a2y, lane + 12);
    float o2x = shflf(a2x, lane + 18), o2y = shflf(a2y, lane + 18);
    c2x = fmaf(f2x, c2x, a2x * i2x);
    c2y = fmaf(f2y, c2y, a2y * i2y);
    float tx = tanhfast(o2x * tanhfast(c2x));   // tanh(h2(999))
    float ty = tanhfast(o2y * tanhfast(c2y));

    // FC + sigmoid (all lanes run the shfl loop; lane 0 stores)
    float bf = b_fc[0];
    float sx = bf, sy = bf;
#pragma unroll
    for (int j = 0; j < H2; j++) {
        float vx = shflf(tx, j);
        float vy = shflf(ty, j);
        float wf = W_fc[j];
        sx = fmaf(vx, wf, sx);
        sy = fmaf(vy, wf, sy);
    }
    if (lane == 0) {
        out[2 * w]     = actf(sx, -LOG2E, 1.f, 0.f);
        out[2 * w + 1] = actf(sy, -LOG2E, 1.f, 0.f);
    }
}

// ============================================================================
extern "C" void kernel_launch(void* const* d_in, const int* in_sizes, int n_in,
                              void* d_out, int out_size) {
    const float* x     = (const float*)d_in[0];
    const float* W_ih1 = (const float*)d_in[1];
    const float* W_hh1 = (const float*)d_in[2];
    const float* b_ih1 = (const float*)d_in[3];
    const float* b_hh1 = (const float*)d_in[4];
    const float* W_ih2 = (const float*)d_in[5];
    const float* W_hh2 = (const float*)d_in[6];
    const float* b_ih2 = (const float*)d_in[7];
    const float* b_hh2 = (const float*)d_in[8];
    const float* W_fc  = (const float*)d_in[9];
    const float* b_fc  = (const float*)d_in[10];
    float* out = (float*)d_out;

    dim3 pgrid(T_STEPS / PCHUNK, NPAIR);   // (8, 1024)
    proj_kernel<<<pgrid, PBLK>>>(x, W_ih1, b_ih1, b_hh1);

    rec_kernel<<<NPAIR, 32>>>(W_hh1, W_ih2, W_hh2, b_ih2, b_hh2, W_fc, b_fc, out);
}

// round 3
// speedup vs baseline: 3.0664x; 1.5872x over previous
#include <cuda_runtime.h>
#include <cstdint>

#define T_STEPS 1000
#define BATCH   2048
#define FEAT    40
#define H1      8
#define H2      6
#define G1      32
#define G2      24
#define NPAIR   1024

#define CT      10                    // timesteps per staged x-chunk
#define NCHUNK  (T_STEPS / CT)        // 100
#define F4ROW   (FEAT / 4)            // 10 float4 per (row, t)
#define SITES   (2 * CT * F4ROW)      // 200 float4 sites per chunk
#define NITER   ((SITES + 31) / 32)   // 7

typedef unsigned long long u64;

// ---------------- f32x2 helpers ----------------
__device__ __forceinline__ u64 pack2(float x, float y) {
    u64 r; asm("mov.b64 %0, {%1, %2};" : "=l"(r) : "f"(x), "f"(y)); return r;
}
__device__ __forceinline__ void unpack2(u64 v, float& x, float& y) {
    asm("mov.b64 {%0, %1}, %2;" : "=f"(x), "=f"(y) : "l"(v));
}
__device__ __forceinline__ u64 fma2(u64 a, u64 b, u64 c) {
    u64 d; asm("fma.rn.f32x2 %0, %1, %2, %3;" : "=l"(d) : "l"(a), "l"(b), "l"(c)); return d;
}
__device__ __forceinline__ u64 mul2(u64 a, u64 b) {
    u64 d; asm("mul.rn.f32x2 %0, %1, %2;" : "=l"(d) : "l"(a), "l"(b)); return d;
}
__device__ __forceinline__ u64 add2(u64 a, u64 b) {
    u64 d; asm("add.rn.f32x2 %0, %1, %2;" : "=l"(d) : "l"(a), "l"(b)); return d;
}

// ---------------- activations: 1 MUFU each ----------------
__device__ __forceinline__ float tanha(float x) {
    float r; asm("tanh.approx.f32 %0, %1;" : "=f"(r) : "f"(x)); return r;
}
// act(x) = ca + cn * tanh(cm * x); sigmoid: (0.5,0.5,0.5); tanh: (1,1,0)
__device__ __forceinline__ float actf(float x, float cm, float cn, float ca) {
    return fmaf(cn, tanha(cm * x), ca);
}

__device__ __forceinline__ float shflf(float v, int src) {
    return __shfl_sync(0xffffffffu, v, src);
}

// input-projection partial: dot(x_row[t], W_ih1[lane]) via pairwise f32x2
__device__ __forceinline__ float xdot(const u64* __restrict__ xr, int tc,
                                      const u64* __restrict__ w2) {
    const ulonglong2* q = reinterpret_cast<const ulonglong2*>(xr + tc * (FEAT / 2));
    ulonglong2 v = q[0];
    u64 a = mul2(w2[0], v.x);
    u64 d = mul2(w2[1], v.y);
#pragma unroll
    for (int p = 1; p < F4ROW; p++) {
        v = q[p];
        a = fma2(w2[2 * p],     v.x, a);
        d = fma2(w2[2 * p + 1], v.y, d);
    }
    a = add2(a, d);
    float ax, ay; unpack2(a, ax, ay);
    return ax + ay;
}

// ============================================================================
// one fused LSTM step: layer1(i) + layer2(i-1)
// ============================================================================
template <int RD>
__device__ __forceinline__ void lstm_step(
    int tc, float en, int lane,
    const u64* __restrict__ xr0, const u64* __restrict__ xr1,
    u64 (*shs)[24],
    const u64* w2, const u64* w1, const u64* wi2, const u64* wh2,
    u64 bias1, u64 bias2,
    float cm1, float cn1, float ca1,
    float cm2, float cn2, float ca2,
    float& c1x, float& c1y, float& c2x, float& c2y)
{
    constexpr int WR = RD ^ 1;

    // ---- input projection for this lane's gate (off the serial chain) ----
    float gin_x = xdot(xr0, tc, w2);
    float gin_y = xdot(xr1, tc, w2);
    u64 g1in = pack2(gin_x, gin_y);

    // ---- layer1 hidden MAC ----
    u64 A = fma2(shs[RD][0], w1[0], bias1);
    u64 B = mul2(shs[RD][1], w1[1]);
    A = fma2(shs[RD][2], w1[2], A);
    B = fma2(shs[RD][3], w1[3], B);
    A = fma2(shs[RD][4], w1[4], A);
    B = fma2(shs[RD][5], w1[5], B);
    A = fma2(shs[RD][6], w1[6], A);
    B = fma2(shs[RD][7], w1[7], B);
    u64 g1 = add2(add2(A, B), g1in);

    // ---- layer2 MAC: bias2 + x2(i-1).wi2 + h2(i-2).wh2 ----
    u64 P = fma2(shs[RD][8],  wi2[0], bias2);
    u64 Q = mul2(shs[RD][9],  wi2[1]);
    u64 R = mul2(shs[RD][10], wi2[2]);
    P = fma2(shs[RD][11], wi2[3], P);
    Q = fma2(shs[RD][12], wi2[4], Q);
    R = fma2(shs[RD][13], wi2[5], R);
    P = fma2(shs[RD][14], wi2[6], P);
    Q = fma2(shs[RD][15], wi2[7], Q);
    R = fma2(shs[RD][16], wh2[0], R);
    P = fma2(shs[RD][17], wh2[1], P);
    Q = fma2(shs[RD][18], wh2[2], Q);
    R = fma2(shs[RD][19], wh2[3], R);
    P = fma2(shs[RD][20], wh2[4], P);
    Q = fma2(shs[RD][21], wh2[5], Q);
    u64 g2 = add2(add2(P, Q), R);

    // ---- activations (1 MUFU each) ----
    float g1x, g1y; unpack2(g1, g1x, g1y);
    float g2x, g2y; unpack2(g2, g2x, g2y);
    float a1x = actf(g1x, cm1, cn1, ca1);
    float a1y = actf(g1y, cm1, cn1, ca1);
    float a2x = actf(g2x, cm2, cn2, ca2);
    float a2y = actf(g2y, cm2, cn2, ca2);

    // ---- gate gathers ----
    float f1x = shflf(a1x, lane + 8),  f1y = shflf(a1y, lane + 8);
    float i1x = shflf(a1x, lane + 16), i1y = shflf(a1y, lane + 16);
    float o1x = shflf(a1x, lane + 24), o1y = shflf(a1y, lane + 24);
    float f2x = shflf(a2x, lane + 6),  f2y = shflf(a2y, lane + 6);
    float i2x = shflf(a2x, lane + 12), i2y = shflf(a2y, lane + 12);
    float o2x = shflf(a2x, lane + 18), o2y = shflf(a2y, lane + 18);

    // ---- layer1 state (valid lanes 0..7) ----
    c1x = fmaf(f1x, c1x, a1x * i1x);
    c1y = fmaf(f1y, c1y, a1y * i1y);
    float h1x = o1x * tanha(c1x);
    float h1y = o1y * tanha(c1y);
    float x2x = tanha(h1x);
    float x2y = tanha(h1y);

    // ---- layer2 state (valid lanes 0..5) ----
    c2x = en * fmaf(f2x, c2x, a2x * i2x);
    c2y = en * fmaf(f2y, c2y, a2y * i2y);
    float h2x = o2x * tanha(c2x);
    float h2y = o2y * tanha(c2y);

    if (lane < H1) {
        shs[WR][lane]     = pack2(h1x, h1y);
        shs[WR][8 + lane] = pack2(x2x, x2y);
    }
    if (lane < H2) shs[WR][16 + lane] = pack2(h2x, h2y);
    __syncwarp();
}

// ============================================================================
// fused kernel: 1 warp per batch pair
// ============================================================================
__global__ void __launch_bounds__(32)
fused_kernel(const float* __restrict__ x,
             const float* __restrict__ W_ih1,
             const float* __restrict__ W_hh1,
             const float* __restrict__ b_ih1,
             const float* __restrict__ b_hh1,
             const float* __restrict__ W_ih2,
             const float* __restrict__ W_hh2,
             const float* __restrict__ b_ih2,
             const float* __restrict__ b_hh2,
             const float* __restrict__ W_fc,
             const float* __restrict__ b_fc,
             float* __restrict__ out) {
    __shared__ u64 shs[2][24];
    __shared__ __align__(16) u64 sx[2][2][CT][FEAT / 2];  // [buf][row][t][pairs]

    int lane = threadIdx.x;
    int w    = blockIdx.x;

    // ---- per-lane weights ----
    // input-proj weights, pairwise packed (NOT duplicated): w2[p]=(W[g][2p],W[g][2p+1])
    u64 w2[FEAT / 2];
    {
        const u64* wrow = reinterpret_cast<const u64*>(W_ih1 + lane * FEAT);
#pragma unroll
        for (int p = 0; p < FEAT / 2; p++) w2[p] = wrow[p];
    }
    u64 w1[H1];
#pragma unroll
    for (int j = 0; j < H1; j++) { float v = W_hh1[lane * H1 + j]; w1[j] = pack2(v, v); }
    u64 wi2[H1], wh2[H2], bias2 = 0ull;
#pragma unroll
    for (int j = 0; j < H1; j++) wi2[j] = 0ull;
#pragma unroll
    for (int j = 0; j < H2; j++) wh2[j] = 0ull;
    if (lane < G2) {
#pragma unroll
        for (int j = 0; j < H1; j++) { float v = W_ih2[lane * H1 + j]; wi2[j] = pack2(v, v); }
#pragma unroll
        for (int j = 0; j < H2; j++) { float v = W_hh2[lane * H2 + j]; wh2[j] = pack2(v, v); }
        float bb = b_ih2[lane] + b_hh2[lane];
        bias2 = pack2(bb, bb);
    }
    float b1s = b_ih1[lane] + b_hh1[lane];
    u64 bias1 = pack2(b1s, b1s);

    // ---- per-lane activation constants (tanh-based) ----
    bool t1 = ((lane >> 3) == 2);
    float cm1 = t1 ? 1.f : 0.5f, cn1 = t1 ? 1.f : 0.5f, ca1 = t1 ? 0.f : 0.5f;
    bool t2 = (lane >= 12 && lane < 18);
    float cm2 = t2 ? 1.f : 0.5f, cn2 = t2 ? 1.f : 0.5f, ca2 = t2 ? 0.f : 0.5f;

    if (lane < 24) shs[1][lane] = 0ull;   // zero state read by step 0

    // ---- x chunk staging pointers ----
    const float4* xb0 = reinterpret_cast<const float4*>(x + (size_t)(2 * w)     * T_STEPS * FEAT);
    const float4* xb1 = reinterpret_cast<const float4*>(x + (size_t)(2 * w + 1) * T_STEPS * FEAT);

    // preload chunk 0 into buffer 0
    {
        float4 f4[NITER];
#pragma unroll
        for (int i = 0; i < NITER; i++) {
            int s = lane + 32 * i;
            if (s < SITES) f4[i] = (s < SITES / 2) ? xb0[s] : xb1[s - SITES / 2];
        }
        float4* sb = reinterpret_cast<float4*>(&sx[0][0][0][0]);
#pragma unroll
        for (int i = 0; i < NITER; i++) {
            int s = lane + 32 * i;
            if (s < SITES) sb[s] = f4[i];
        }
    }
    __syncwarp();

    float c1x = 0.f, c1y = 0.f, c2x = 0.f, c2y = 0.f;

#pragma unroll 1
    for (int c = 0; c < NCHUNK; c++) {
        int b = c & 1;
        const u64* xr0 = &sx[b][0][0][0];
        const u64* xr1 = &sx[b][1][0][0];

        // issue prefetch LDGs for chunk c+1 (clamped on last chunk)
        int cn = (c + 1 < NCHUNK) ? c + 1 : c;
        const float4* p0 = xb0 + cn * (CT * F4ROW);
        const float4* p1 = xb1 + cn * (CT * F4ROW);
        float4 f4[NITER];
#pragma unroll
        for (int i = 0; i < NITER; i++) {
            int s = lane + 32 * i;
            if (s < SITES) f4[i] = (s < SITES / 2) ? p0[s] : p1[s - SITES / 2];
        }

        float en0 = (c == 0) ? 0.f : 1.f;
        // steps 0..3 (LDG latency hides underneath)
        lstm_step<1>(0, en0, lane, xr0, xr1, shs, w2, w1, wi2, wh2, bias1, bias2,
                     cm1, cn1, ca1, cm2, cn2, ca2, c1x, c1y, c2x, c2y);
        lstm_step<0>(1, 1.f, lane, xr0, xr1, shs, w2, w1, wi2, wh2, bias1, bias2,
                     cm1, cn1, ca1, cm2, cn2, ca2, c1x, c1y, c2x, c2y);
        lstm_step<1>(2, 1.f, lane, xr0, xr1, shs, w2, w1, wi2, wh2, bias1, bias2,
                     cm1, cn1, ca1, cm2, cn2, ca2, c1x, c1y, c2x, c2y);
        lstm_step<0>(3, 1.f, lane, xr0, xr1, shs, w2, w1, wi2, wh2, bias1, bias2,
                     cm1, cn1, ca1, cm2, cn2, ca2, c1x, c1y, c2x, c2y);

        // stash prefetched chunk into the other buffer
        {
            float4* sb = reinterpret_cast<float4*>(&sx[b ^ 1][0][0][0]);
#pragma unroll
            for (int i = 0; i < NITER; i++) {
                int s = lane + 32 * i;
                if (s < SITES) sb[s] = f4[i];
            }
        }

        // steps 4..9
#pragma unroll 3
        for (int k = 2; k < 5; k++) {
            lstm_step<1>(2 * k,     1.f, lane, xr0, xr1, shs, w2, w1, wi2, wh2, bias1, bias2,
                         cm1, cn1, ca1, cm2, cn2, ca2, c1x, c1y, c2x, c2y);
            lstm_step<0>(2 * k + 1, 1.f, lane, xr0, xr1, shs, w2, w1, wi2, wh2, bias1, bias2,
                         cm1, cn1, ca1, cm2, cn2, ca2, c1x, c1y, c2x, c2y);
        }
    }

    // ---- epilogue: layer2(999) from slab[1] (x2(999), h2(998)) ----
    u64 P = fma2(shs[1][8],  wi2[0], bias2);
    u64 Q = mul2(shs[1][9],  wi2[1]);
    u64 R = mul2(shs[1][10], wi2[2]);
    P = fma2(shs[1][11], wi2[3], P);
    Q = fma2(shs[1][12], wi2[4], Q);
    R = fma2(shs[1][13], wi2[5], R);
    P = fma2(shs[1][14], wi2[6], P);
    Q = fma2(shs[1][15], wi2[7], Q);
    R = fma2(shs[1][16], wh2[0], R);
    P = fma2(shs[1][17], wh2[1], P);
    Q = fma2(shs[1][18], wh2[2], Q);
    R = fma2(shs[1][19], wh2[3], R);
    P = fma2(shs[1][20], wh2[4], P);
    Q = fma2(shs[1][21], wh2[5], Q);
    u64 g2 = add2(add2(P, Q), R);

    float g2x, g2y; unpack2(g2, g2x, g2y);
    float a2x = actf(g2x, cm2, cn2, ca2);
    float a2y = actf(g2y, cm2, cn2, ca2);
    float f2x = shflf(a2x, lane + 6),  f2y = shflf(a2y, lane + 6);
    float i2x = shflf(a2x, lane + 12), i2y = shflf(a2y, lane + 12);
    float o2x = shflf(a2x, lane + 18), o2y = shflf(a2y, lane + 18);
    c2x = fmaf(f2x, c2x, a2x * i2x);
    c2y = fmaf(f2y, c2y, a2y * i2y);
    float tx = tanha(o2x * tanha(c2x));   // tanh(h2(999))
    float ty = tanha(o2y * tanha(c2y));

    // FC + sigmoid
    float bf = b_fc[0];
    float sx_ = bf, sy_ = bf;
#pragma unroll
    for (int j = 0; j < H2; j++) {
        float vx = shflf(tx, j);
        float vy = shflf(ty, j);
        float wf = W_fc[j];
        sx_ = fmaf(vx, wf, sx_);
        sy_ = fmaf(vy, wf, sy_);
    }
    if (lane == 0) {
        out[2 * w]     = actf(sx_, 0.5f, 0.5f, 0.5f);
        out[2 * w + 1] = actf(sy_, 0.5f, 0.5f, 0.5f);
    }
}

// ============================================================================
extern "C" void kernel_launch(void* const* d_in, const int* in_sizes, int n_in,
                              void* d_out, int out_size) {
    const float* x     = (const float*)d_in[0];
    const float* W_ih1 = (const float*)d_in[1];
    const float* W_hh1 = (const float*)d_in[2];
    const float* b_ih1 = (const float*)d_in[3];
    const float* b_hh1 = (const float*)d_in[4];
    const float* W_ih2 = (const float*)d_in[5];
    const float* W_hh2 = (const float*)d_in[6];
    const float* b_ih2 = (const float*)d_in[7];
    const float* b_hh2 = (const float*)d_in[8];
    const float* W_fc  = (const float*)d_in[9];
    const float* b_fc  = (const float*)d_in[10];
    float* out = (float*)d_out;

    fused_kernel<<<NPAIR, 32>>>(x, W_ih1, W_hh1, b_ih1, b_hh1,
                                W_ih2, W_hh2, b_ih2, b_hh2, W_fc, b_fc, out);
}